// round 7
// baseline (speedup 1.0000x reference)
#include <cuda_runtime.h>
#include <cfloat>

namespace {
constexpr int kB  = 2;
constexpr int kH  = 8;
constexpr int kS  = 2048;
constexpr int kDK = 32;
constexpr int kDM = 256;
constexpr int kNRow = kB * kS;           // 4096
constexpr float kScale = 0.17677669529663687f;  // 1/sqrt(32)

constexpr int kWarps   = 8;
constexpr int kThreads = kWarps * 32;    // 256
constexpr int kQW      = 8;              // queries per warp
constexpr int kQCta    = kWarps * kQW;   // 64 queries per CTA
constexpr int kCap     = 128;            // candidate list capacity per query

constexpr int kSmemK   = 1024 * 16;                    // K tile: 1024 float4
constexpr int kSmemQ   = kQCta * 8 * 16;               // 512 float4
constexpr int kSmemL   = kWarps * kQW * kCap * 8;      // candidate lists (float2)
constexpr int kSmemBytes = kSmemK + kSmemQ + kSmemL;   // 90112 B
}

// Scratch: projected Q/K/V in [b,h,s,d] layout (4 MB each).
__device__ float g_q[kB * kH * kS * kDK];
__device__ float g_k[kB * kH * kS * kDK];
__device__ float g_v[kB * kH * kS * kDK];

// ---------------------------------------------------------------------------
// Projection GEMM (unchanged): out = X @ W^T + bias -> [b,h,s,d]
// ---------------------------------------------------------------------------
__global__ __launch_bounds__(256)
void proj_kernel(const float* __restrict__ xq, const float* __restrict__ xk,
                 const float* __restrict__ xv,
                 const float* __restrict__ wq, const float* __restrict__ bq,
                 const float* __restrict__ wk, const float* __restrict__ bk,
                 const float* __restrict__ wv, const float* __restrict__ bv)
{
    constexpr int PBM = 128, PBN = 64, PBK = 16;
    __shared__ float As[PBK][PBM];
    __shared__ float Bs[PBK][PBN];

    const int z = blockIdx.z;
    const float* __restrict__ X    = (z == 0) ? xq : (z == 1) ? xk : xv;
    const float* __restrict__ W    = (z == 0) ? wq : (z == 1) ? wk : wv;
    const float* __restrict__ bias = (z == 0) ? bq : (z == 1) ? bk : bv;
    float* __restrict__ out        = (z == 0) ? g_q : (z == 1) ? g_k : g_v;

    const int n0 = blockIdx.y * PBM;
    const int c0 = blockIdx.x * PBN;
    const int tid = threadIdx.x;
    const int tx = tid & 15;
    const int ty = tid >> 4;

    float acc[8][4];
    #pragma unroll
    for (int i = 0; i < 8; ++i)
        #pragma unroll
        for (int j = 0; j < 4; ++j) acc[i][j] = 0.0f;

    for (int k0 = 0; k0 < kDM; k0 += PBK) {
        #pragma unroll
        for (int r = 0; r < 2; ++r) {
            int f   = tid + r * 256;
            int row = f >> 2;
            int kk  = (f & 3) * 4;
            float4 v = *reinterpret_cast<const float4*>(X + (n0 + row) * kDM + k0 + kk);
            As[kk + 0][row] = v.x; As[kk + 1][row] = v.y;
            As[kk + 2][row] = v.z; As[kk + 3][row] = v.w;
        }
        {
            int n  = tid >> 2;
            int kk = (tid & 3) * 4;
            float4 v = *reinterpret_cast<const float4*>(W + (c0 + n) * kDM + k0 + kk);
            Bs[kk + 0][n] = v.x; Bs[kk + 1][n] = v.y;
            Bs[kk + 2][n] = v.z; Bs[kk + 3][n] = v.w;
        }
        __syncthreads();

        #pragma unroll
        for (int k = 0; k < PBK; ++k) {
            float4 a0 = *reinterpret_cast<const float4*>(&As[k][ty * 8]);
            float4 a1 = *reinterpret_cast<const float4*>(&As[k][ty * 8 + 4]);
            float4 bb = *reinterpret_cast<const float4*>(&Bs[k][tx * 4]);
            float a[8] = {a0.x, a0.y, a0.z, a0.w, a1.x, a1.y, a1.z, a1.w};
            float b[4] = {bb.x, bb.y, bb.z, bb.w};
            #pragma unroll
            for (int i = 0; i < 8; ++i)
                #pragma unroll
                for (int j = 0; j < 4; ++j)
                    acc[i][j] = fmaf(a[i], b[j], acc[i][j]);
        }
        __syncthreads();
    }

    #pragma unroll
    for (int i = 0; i < 8; ++i) {
        const int row = n0 + ty * 8 + i;
        const int bb  = row / kS;
        const int ss  = row % kS;
        #pragma unroll
        for (int j = 0; j < 4; ++j) {
            const int col = c0 + tx * 4 + j;
            const int h = col >> 5, d = col & 31;
            out[((bb * kH + h) * kS + ss) * kDK + d] = acc[i][j] + bias[col];
        }
    }
}

// ---------------------------------------------------------------------------
// Warp-uniform list prune: drop entries <= thr. Rare; out of line.
// ---------------------------------------------------------------------------
__device__ __noinline__ int prune_list(float2* list, int n, float thr,
                                       int lane, unsigned lmask)
{
    float2 e[4];
    #pragma unroll
    for (int g = 0; g < 4; ++g) {
        int idx = g * 32 + lane;
        e[g] = (idx < n) ? list[idx] : make_float2(-FLT_MAX, 0.0f);
    }
    __syncwarp();
    int nc = 0;
    #pragma unroll
    for (int g = 0; g < 4; ++g) {
        bool keep = (g * 32 + lane < n) && (e[g].x > thr);
        unsigned km = __ballot_sync(0xffffffffu, keep);
        if (keep) list[nc + __popc(km & lmask)] = e[g];
        nc += __popc(km);
    }
    __syncwarp();
    return nc;
}

// ---------------------------------------------------------------------------
// Exact streaming fallback (taken only on candidate-list overflow; ~never).
// Recomputes scores from gmem; Michelot then ballot-pop AV.
// ---------------------------------------------------------------------------
__device__ __noinline__ float slow_query(const float* __restrict__ Kbh,
                                         const float* __restrict__ Vbh,
                                         const float4* __restrict__ Qw,
                                         float m, int lane)
{
    float tau = m - 1.0f;
    int prev = -1;
    for (int it = 0; it < 80; ++it) {
        float sum = 0.0f; int c = 0;
        for (int t = 0; t < kS / 32; ++t) {
            const int j = t * 32 + lane;
            float s = 0.0f;
            #pragma unroll
            for (int d4 = 0; d4 < 8; ++d4) {
                float4 qv = Qw[d4];
                float4 kv = __ldg(reinterpret_cast<const float4*>(Kbh + j * kDK) + d4);
                s += kv.x * qv.x + kv.y * qv.y + kv.z * qv.z + kv.w * qv.w;
            }
            s *= kScale;
            if (s > tau) { sum += s; ++c; }
        }
        #pragma unroll
        for (int o = 16; o; o >>= 1) {
            sum += __shfl_xor_sync(0xffffffffu, sum, o);
            c   += __shfl_xor_sync(0xffffffffu, c, o);
        }
        if (c == prev || c == 0) break;
        tau = (sum - 1.0f) / (float)c;
        prev = c;
    }
    float a = 0.0f;
    for (int t = 0; t < kS / 32; ++t) {
        const int j = t * 32 + lane;
        float s = 0.0f;
        #pragma unroll
        for (int d4 = 0; d4 < 8; ++d4) {
            float4 qv = Qw[d4];
            float4 kv = __ldg(reinterpret_cast<const float4*>(Kbh + j * kDK) + d4);
            s += kv.x * qv.x + kv.y * qv.y + kv.z * qv.z + kv.w * qv.w;
        }
        s *= kScale;
        float w = s - tau;
        unsigned mk = __ballot_sync(0xffffffffu, w > 0.0f);
        while (mk) {
            int b = __ffs(mk) - 1;
            mk &= mk - 1;
            float wb = __shfl_sync(0xffffffffu, w, b);
            a = fmaf(wb, __ldg(Vbh + (t * 32 + b) * kDK + lane), a);
        }
    }
    return a;
}

// ---------------------------------------------------------------------------
// Fused sparsemax attention, STREAMING: 8 queries/warp, no score storage.
// Per K tile: compute 4 scores/lane/query, update running max, append
// candidates (s > max-1) to smem lists (prune-on-full; exact superset).
// Then per query: Michelot on <=128 candidates + short dense AV.
// ---------------------------------------------------------------------------
__global__ __launch_bounds__(kThreads, 2)
void attn_kernel(float* __restrict__ out)
{
    extern __shared__ char smem[];
    float4* __restrict__ Ks4   = reinterpret_cast<float4*>(smem);             // [d4][j^d4]
    float4* __restrict__ Qs4   = reinterpret_cast<float4*>(smem + kSmemK);    // [q][d4]
    float2* __restrict__ Lists = reinterpret_cast<float2*>(smem + kSmemK + kSmemQ);

    const int bh   = blockIdx.y;
    const int warp = threadIdx.x >> 5;
    const int lane = threadIdx.x & 31;
    const int tid  = threadIdx.x;
    const unsigned lmask = (1u << lane) - 1u;

    const int q0 = blockIdx.x * kQCta;

    const float* __restrict__ Kbh = g_k + bh * kS * kDK;
    const float* __restrict__ Vbh = g_v + bh * kS * kDK;

    // Stage the CTA's 64 q rows into shared (512 float4)
    #pragma unroll
    for (int r = 0; r < 2; ++r) {
        int i = tid + r * kThreads;
        int qq = i >> 3, d4 = i & 7;
        Qs4[i] = *reinterpret_cast<const float4*>(
            g_q + (bh * kS + q0 + qq) * kDK + d4 * 4);
    }

    float m[kQW];
    int   cnt[kQW];
    #pragma unroll
    for (int q = 0; q < kQW; ++q) { m[q] = -FLT_MAX; cnt[q] = 0; }
    unsigned ovfm = 0;

    #pragma unroll 1
    for (int t = 0; t < 16; ++t) {
        __syncthreads();
        // Fill K tile: 1024 float4, transposed + XOR-swizzled
        #pragma unroll
        for (int r = 0; r < 4; ++r) {
            int f  = tid + r * kThreads;
            int j  = f >> 3;
            int d4 = f & 7;
            Ks4[d4 * 128 + (j ^ d4)] =
                *reinterpret_cast<const float4*>(Kbh + (t * 128 + j) * kDK + d4 * 4);
        }
        __syncthreads();

        float acc[kQW][4];
        #pragma unroll
        for (int q = 0; q < kQW; ++q)
            #pragma unroll
            for (int k = 0; k < 4; ++k) acc[q][k] = 0.0f;

        #pragma unroll 2
        for (int dd = 0; dd < 8; ++dd) {
            const float4 kv0 = Ks4[dd * 128 + ((lane      ) ^ dd)];
            const float4 kv1 = Ks4[dd * 128 + ((lane +  32) ^ dd)];
            const float4 kv2 = Ks4[dd * 128 + ((lane +  64) ^ dd)];
            const float4 kv3 = Ks4[dd * 128 + ((lane +  96) ^ dd)];
            #pragma unroll
            for (int q = 0; q < kQW; ++q) {
                const float4 qv = Qs4[(warp * kQW + q) * 8 + dd];   // broadcast
                acc[q][0] = fmaf(kv0.x, qv.x, acc[q][0]);
                acc[q][0] = fmaf(kv0.y, qv.y, acc[q][0]);
                acc[q][0] = fmaf(kv0.z, qv.z, acc[q][0]);
                acc[q][0] = fmaf(kv0.w, qv.w, acc[q][0]);
                acc[q][1] = fmaf(kv1.x, qv.x, acc[q][1]);
                acc[q][1] = fmaf(kv1.y, qv.y, acc[q][1]);
                acc[q][1] = fmaf(kv1.z, qv.z, acc[q][1]);
                acc[q][1] = fmaf(kv1.w, qv.w, acc[q][1]);
                acc[q][2] = fmaf(kv2.x, qv.x, acc[q][2]);
                acc[q][2] = fmaf(kv2.y, qv.y, acc[q][2]);
                acc[q][2] = fmaf(kv2.z, qv.z, acc[q][2]);
                acc[q][2] = fmaf(kv2.w, qv.w, acc[q][2]);
                acc[q][3] = fmaf(kv3.x, qv.x, acc[q][3]);
                acc[q][3] = fmaf(kv3.y, qv.y, acc[q][3]);
                acc[q][3] = fmaf(kv3.z, qv.z, acc[q][3]);
                acc[q][3] = fmaf(kv3.w, qv.w, acc[q][3]);
            }
        }

        // Per-query: scale, running max, candidate append
        #pragma unroll
        for (int q = 0; q < kQW; ++q) {
            float ss[4];
            #pragma unroll
            for (int k = 0; k < 4; ++k) ss[k] = acc[q][k] * kScale;
            float lm = fmaxf(fmaxf(ss[0], ss[1]), fmaxf(ss[2], ss[3]));
            #pragma unroll
            for (int o = 16; o; o >>= 1)
                lm = fmaxf(lm, __shfl_xor_sync(0xffffffffu, lm, o));
            m[q] = fmaxf(m[q], lm);
            const float thr = m[q] - 1.0f;
            float2* __restrict__ Lq = Lists + (warp * kQW + q) * kCap;
            #pragma unroll
            for (int k = 0; k < 4; ++k) {
                const bool c = ss[k] > thr;
                const unsigned mk = __ballot_sync(0xffffffffu, c);
                if (mk && !(ovfm & (1u << q))) {
                    const int pc = __popc(mk);
                    int n = cnt[q];
                    if (n + pc > kCap) {
                        n = prune_list(Lq, n, thr, lane, lmask);
                        if (n + pc > kCap) { ovfm |= (1u << q); cnt[q] = n; continue; }
                    }
                    if (c)
                        Lq[n + __popc(mk & lmask)] =
                            make_float2(ss[k], __int_as_float(t * 128 + k * 32 + lane));
                    cnt[q] = n + pc;
                }
            }
        }
    }

    // Per-query finalize: Michelot on candidates + dense AV over the list
    const int bb = bh >> 3;
    const int h  = bh & 7;
    #pragma unroll
    for (int q = 0; q < kQW; ++q) {
        float2* __restrict__ Lq = Lists + (warp * kQW + q) * kCap;
        const int n = cnt[q];
        float a;
        if (!(ovfm & (1u << q))) {
            float c0 = (lane      < n) ? Lq[lane     ].x : -FLT_MAX;
            float c1 = (lane + 32 < n) ? Lq[lane + 32].x : -FLT_MAX;
            float c2 = (lane + 64 < n) ? Lq[lane + 64].x : -FLT_MAX;
            float c3 = (lane + 96 < n) ? Lq[lane + 96].x : -FLT_MAX;
            float tau = m[q] - 1.0f;
            int prev = -1;
            for (int it = 0; it < 80; ++it) {
                float sum = 0.0f; int c = 0;
                if (c0 > tau) { sum += c0; ++c; }
                if (c1 > tau) { sum += c1; ++c; }
                if (c2 > tau) { sum += c2; ++c; }
                if (c3 > tau) { sum += c3; ++c; }
                #pragma unroll
                for (int o = 16; o; o >>= 1) {
                    sum += __shfl_xor_sync(0xffffffffu, sum, o);
                    c   += __shfl_xor_sync(0xffffffffu, c, o);
                }
                if (c == prev || c == 0) break;
                tau = (sum - 1.0f) / (float)c;
                prev = c;
            }
            // Dense AV over candidate list (weights clamp to 0 below tau)
            float a0 = 0.0f, a1 = 0.0f;
            int ci = 0;
            for (; ci + 2 <= n; ci += 2) {
                float2 p0 = Lq[ci], p1 = Lq[ci + 1];
                float w0 = fmaxf(p0.x - tau, 0.0f);
                float w1 = fmaxf(p1.x - tau, 0.0f);
                a0 = fmaf(w0, __ldg(Vbh + __float_as_int(p0.y) * kDK + lane), a0);
                a1 = fmaf(w1, __ldg(Vbh + __float_as_int(p1.y) * kDK + lane), a1);
            }
            if (ci < n) {
                float2 p0 = Lq[ci];
                float w0 = fmaxf(p0.x - tau, 0.0f);
                a0 = fmaf(w0, __ldg(Vbh + __float_as_int(p0.y) * kDK + lane), a0);
            }
            a = a0 + a1;
        } else {
            a = slow_query(Kbh, Vbh, &Qs4[(warp * kQW + q) * 8], m[q], lane);
        }
        out[(bb * kS + (q0 + warp * kQW + q)) * kDM + h * kDK + lane] = a;
    }
}

// ---------------------------------------------------------------------------
extern "C" void kernel_launch(void* const* d_in, const int* in_sizes, int n_in,
                              void* d_out, int out_size)
{
    const float* query = (const float*)d_in[0];
    const float* key   = (const float*)d_in[1];
    const float* value = (const float*)d_in[2];
    const float* Wq    = (const float*)d_in[3];
    const float* bq    = (const float*)d_in[4];
    const float* Wk    = (const float*)d_in[5];
    const float* bk    = (const float*)d_in[6];
    const float* Wv    = (const float*)d_in[7];
    const float* bv    = (const float*)d_in[8];
    float* out = (float*)d_out;

    dim3 pgrid(kDM / 64, kNRow / 128, 3);      // (4, 32, 3)
    proj_kernel<<<pgrid, 256>>>(query, key, value, Wq, bq, Wk, bk, Wv, bv);

    cudaFuncSetAttribute(attn_kernel,
                         cudaFuncAttributeMaxDynamicSharedMemorySize, kSmemBytes);
    dim3 agrid(kS / kQCta, kB * kH);           // (32, 16)
    attn_kernel<<<agrid, kThreads, kSmemBytes>>>(out);

    (void)in_sizes; (void)n_in; (void)out_size;
}